// round 3
// baseline (speedup 1.0000x reference)
#include <cuda_runtime.h>
#include <cuda_bf16.h>

// Problem constants
#define BB 64      // batch
#define NN 512     // tokens
#define EE 512     // embed dim
#define DD 1024    // 2E
#define TT 64      // decode steps

// ---------------- device scratch (allowed: __device__ globals) ----------------
__device__ float g_enc[(size_t)BB * EE * NN];   // [b][e][n]  64 MB, L2-resident
__device__ float g_dec[BB * DD];                // current decoder input
__device__ float g_hx [BB * EE];
__device__ float g_q  [BB * EE];
__device__ float g_scores[BB * NN];

// ---------------- packed fp32x2 helpers (sm_103a FFMA2) ----------------
__device__ __forceinline__ unsigned long long pack2(float x, float y) {
    unsigned long long r;
    asm("mov.b64 %0, {%1,%2};" : "=l"(r) : "f"(x), "f"(y));
    return r;
}
__device__ __forceinline__ void unpack2(unsigned long long v, float& x, float& y) {
    asm("mov.b64 {%0,%1}, %2;" : "=f"(x), "=f"(y) : "l"(v));
}
__device__ __forceinline__ void ffma2(unsigned long long& d, unsigned long long a, unsigned long long b) {
    asm("fma.rn.f32x2 %0, %1, %2, %0;" : "+l"(d) : "l"(a), "l"(b));
}

__device__ __forceinline__ float warp_sum(float v) {
#pragma unroll
    for (int o = 16; o; o >>= 1) v += __shfl_xor_sync(0xffffffffu, v, o);
    return v;
}
__device__ __forceinline__ float sigmoidf_acc(float x) {
    return 1.0f / (1.0f + expf(-x));
}

// =====================================================================
// K1: enc_t[b][e][n] = be[e] + sum_d te[b][n][d] * We[e][d]
// 128x128 tile per block, 8x8 micro-tile per thread, FFMA2 packed pairs on n.
// grid (N/128=4, E/128=4, B=64), block 256
// =====================================================================
__global__ __launch_bounds__(256) void enc_kernel(
    const float* __restrict__ te, const float* __restrict__ We,
    const float* __restrict__ be)
{
    const int b  = blockIdx.z;
    const int n0 = blockIdx.x * 128;
    const int e0 = blockIdx.y * 128;

    __shared__ __align__(16) float As[16][132];   // We tile, [k][e_local]
    __shared__ __align__(16) float Bs[16][132];   // te tile, [k][n_local]

    const int tid = threadIdx.x;
    const int ty  = tid >> 4;     // 0..15 -> e micro-row
    const int tx  = tid & 15;     // 0..15 -> n micro-col

    unsigned long long acc[8][4];
#pragma unroll
    for (int i = 0; i < 8; i++)
#pragma unroll
        for (int j = 0; j < 4; j++) acc[i][j] = 0ULL;

    const int lrow = tid >> 2;          // 0..63
    const int lk4  = (tid & 3) * 4;     // 0,4,8,12
    const float* Aptr = We + (size_t)(e0 + lrow) * DD + lk4;
    const float* Bptr = te + ((size_t)b * NN + (n0 + lrow)) * DD + lk4;

    for (int k0 = 0; k0 < DD; k0 += 16) {
        float4 a0 = *(const float4*)(Aptr + k0);
        float4 a1 = *(const float4*)(Aptr + k0 + (size_t)64 * DD);
        float4 c0 = *(const float4*)(Bptr + k0);
        float4 c1 = *(const float4*)(Bptr + k0 + (size_t)64 * DD);
        As[lk4 + 0][lrow]      = a0.x; As[lk4 + 1][lrow]      = a0.y;
        As[lk4 + 2][lrow]      = a0.z; As[lk4 + 3][lrow]      = a0.w;
        As[lk4 + 0][lrow + 64] = a1.x; As[lk4 + 1][lrow + 64] = a1.y;
        As[lk4 + 2][lrow + 64] = a1.z; As[lk4 + 3][lrow + 64] = a1.w;
        Bs[lk4 + 0][lrow]      = c0.x; Bs[lk4 + 1][lrow]      = c0.y;
        Bs[lk4 + 2][lrow]      = c0.z; Bs[lk4 + 3][lrow]      = c0.w;
        Bs[lk4 + 0][lrow + 64] = c1.x; Bs[lk4 + 1][lrow + 64] = c1.y;
        Bs[lk4 + 2][lrow + 64] = c1.z; Bs[lk4 + 3][lrow + 64] = c1.w;
        __syncthreads();

#pragma unroll
        for (int kk = 0; kk < 16; kk++) {
            float4 av0 = *(const float4*)&As[kk][ty * 8];
            float4 av1 = *(const float4*)&As[kk][ty * 8 + 4];
            float4 bv0 = *(const float4*)&Bs[kk][tx * 8];
            float4 bv1 = *(const float4*)&Bs[kk][tx * 8 + 4];
            unsigned long long bp0 = pack2(bv0.x, bv0.y);
            unsigned long long bp1 = pack2(bv0.z, bv0.w);
            unsigned long long bp2 = pack2(bv1.x, bv1.y);
            unsigned long long bp3 = pack2(bv1.z, bv1.w);
            float av[8] = {av0.x, av0.y, av0.z, av0.w, av1.x, av1.y, av1.z, av1.w};
#pragma unroll
            for (int i = 0; i < 8; i++) {
                unsigned long long ad = pack2(av[i], av[i]);
                ffma2(acc[i][0], ad, bp0);
                ffma2(acc[i][1], ad, bp1);
                ffma2(acc[i][2], ad, bp2);
                ffma2(acc[i][3], ad, bp3);
            }
        }
        __syncthreads();
    }

#pragma unroll
    for (int i = 0; i < 8; i++) {
        const int e = e0 + ty * 8 + i;
        const float bias = __ldg(&be[e]);
        float* orow = g_enc + ((size_t)b * EE + e) * NN + n0 + tx * 8;
#pragma unroll
        for (int j = 0; j < 4; j++) {
            float x, y;
            unpack2(acc[i][j], x, y);
            float2 v = make_float2(x + bias, y + bias);
            *(float2*)(orow + 2 * j) = v;
        }
    }
}

// =====================================================================
// K0: dec <- encoded_document  (step 0 input). grid 64, block 256
// =====================================================================
__global__ void init_dec_kernel(const float* __restrict__ encdoc)
{
    const int b = blockIdx.x;
    ((float4*)(g_dec + b * DD))[threadIdx.x] =
        ((const float4*)(encdoc + (size_t)b * DD))[threadIdx.x];
}

// =====================================================================
// K2: hx[b][e] from zero-state LSTMCell (f-gate dead).
// Warp per output. grid 4096, block 256 (8 warps, all same b).
// =====================================================================
__global__ __launch_bounds__(256) void hx_kernel(
    const float* __restrict__ W_ih, const float* __restrict__ b_ih,
    const float* __restrict__ b_hh)
{
    __shared__ __align__(16) float xs[DD];
    const int gw   = blockIdx.x * 8 + (threadIdx.x >> 5);
    const int b    = gw >> 9;
    const int e    = gw & 511;
    const int lane = threadIdx.x & 31;

    ((float4*)xs)[threadIdx.x] = ((const float4*)(g_dec + b * DD))[threadIdx.x];
    __syncthreads();

    float ai = 0.f, ag = 0.f, ao = 0.f;
    const float* Wi = W_ih + (size_t)e * DD;
    const float* Wg = W_ih + (size_t)(2 * EE + e) * DD;
    const float* Wo = W_ih + (size_t)(3 * EE + e) * DD;
#pragma unroll
    for (int it = 0; it < 8; it++) {
        const int k = it * 128 + lane * 4;
        float4 x  = *(const float4*)&xs[k];
        float4 wi = __ldg((const float4*)(Wi + k));
        float4 wg = __ldg((const float4*)(Wg + k));
        float4 wo = __ldg((const float4*)(Wo + k));
        ai = fmaf(x.x, wi.x, fmaf(x.y, wi.y, fmaf(x.z, wi.z, fmaf(x.w, wi.w, ai))));
        ag = fmaf(x.x, wg.x, fmaf(x.y, wg.y, fmaf(x.z, wg.z, fmaf(x.w, wg.w, ag))));
        ao = fmaf(x.x, wo.x, fmaf(x.y, wo.y, fmaf(x.z, wo.z, fmaf(x.w, wo.w, ao))));
    }
    ai = warp_sum(ai);
    ag = warp_sum(ag);
    ao = warp_sum(ao);
    if (lane == 0) {
        const float gi = ai + __ldg(&b_ih[e])            + __ldg(&b_hh[e]);
        const float gg = ag + __ldg(&b_ih[2 * EE + e])   + __ldg(&b_hh[2 * EE + e]);
        const float go = ao + __ldg(&b_ih[3 * EE + e])   + __ldg(&b_hh[3 * EE + e]);
        const float c  = sigmoidf_acc(gi) * tanhf(gg);
        g_hx[b * EE + e] = sigmoidf_acc(go) * tanhf(c);
    }
}

// =====================================================================
// K3: q[b][e] = hx[b] . Wd[e] + bd[e]. Warp per output. grid 4096, block 256
// =====================================================================
__global__ __launch_bounds__(256) void q_kernel(
    const float* __restrict__ Wd, const float* __restrict__ bd)
{
    __shared__ __align__(16) float hs[EE];
    const int gw   = blockIdx.x * 8 + (threadIdx.x >> 5);
    const int b    = gw >> 9;
    const int e    = gw & 511;
    const int lane = threadIdx.x & 31;

    if (threadIdx.x < 128)
        ((float4*)hs)[threadIdx.x] = ((const float4*)(g_hx + b * EE))[threadIdx.x];
    __syncthreads();

    float acc = 0.f;
    const float* W = Wd + (size_t)e * EE;
#pragma unroll
    for (int it = 0; it < 4; it++) {
        const int k = it * 128 + lane * 4;
        float4 h = *(const float4*)&hs[k];
        float4 w = __ldg((const float4*)(W + k));
        acc = fmaf(h.x, w.x, fmaf(h.y, w.y, fmaf(h.z, w.z, fmaf(h.w, w.w, acc))));
    }
    acc = warp_sum(acc);
    if (lane == 0) g_q[b * EE + e] = acc + __ldg(&bd[e]);
}

// =====================================================================
// K4: scores[b][n] = br + sum_e wr[e] * tanh(q[b][e] + enc[b][e][n])
// block: 256 thr = 4 e-quarters x 64 n. grid (N/64=8, B=64)
// enc reads are fully coalesced (n contiguous) and L2-resident.
// =====================================================================
__global__ __launch_bounds__(256) void attn_kernel(
    const float* __restrict__ wr, const float* __restrict__ br)
{
    __shared__ float qs[EE];
    __shared__ float ws[EE];
    __shared__ float part[4][64];

    const int b  = blockIdx.y;
    const int nl = threadIdx.x & 63;
    const int n  = blockIdx.x * 64 + nl;
    const int qr = threadIdx.x >> 6;   // e-quarter 0..3

    qs[threadIdx.x]       = g_q[b * EE + threadIdx.x];
    qs[threadIdx.x + 256] = g_q[b * EE + threadIdx.x + 256];
    ws[threadIdx.x]       = __ldg(&wr[threadIdx.x]);
    ws[threadIdx.x + 256] = __ldg(&wr[threadIdx.x + 256]);
    __syncthreads();

    const float* p = g_enc + ((size_t)b * EE + qr * 128) * NN + n;
    float acc = 0.f;
#pragma unroll 8
    for (int e = 0; e < 128; e++) {
        const float v  = __ldg(p + (size_t)e * NN);
        const int   eg = (qr << 7) + e;
        acc = fmaf(ws[eg], tanhf(v + qs[eg]), acc);
    }
    part[qr][nl] = acc;
    __syncthreads();

    if (threadIdx.x < 64) {
        const float s = part[0][threadIdx.x] + part[1][threadIdx.x] +
                        part[2][threadIdx.x] + part[3][threadIdx.x] + __ldg(br);
        g_scores[b * NN + blockIdx.x * 64 + threadIdx.x] = s;
    }
}

// =====================================================================
// K5: per-b log_softmax + argmax (first-index tie-break) + gather next dec.
// grid 64, block 512
// =====================================================================
__global__ __launch_bounds__(512) void softmax_kernel(
    const float* __restrict__ te, float* __restrict__ out,
    int t, int write_idx)
{
    __shared__ float sv[NN];
    __shared__ int   si[NN];
    __shared__ float red[NN];

    const int b = blockIdx.x;
    const int n = threadIdx.x;

    const float s = g_scores[b * NN + n];
    sv[n] = s;
    si[n] = n;
    __syncthreads();

#pragma unroll
    for (int o = 256; o > 0; o >>= 1) {
        if (n < o) {
            const float v2 = sv[n + o];
            const int   i2 = si[n + o];
            if (v2 > sv[n] || (v2 == sv[n] && i2 < si[n])) { sv[n] = v2; si[n] = i2; }
        }
        __syncthreads();
    }
    const float m   = sv[0];
    const int   idx = si[0];

    red[n] = expf(s - m);
    __syncthreads();
#pragma unroll
    for (int o = 256; o > 0; o >>= 1) {
        if (n < o) red[n] += red[n + o];
        __syncthreads();
    }
    const float lse = m + logf(red[0]);

    out[((size_t)b * TT + t) * NN + n] = s - lse;

    // gather next decoder input: token_embeddings[b, idx, :] (1024 floats)
    const float2* src = (const float2*)(te + ((size_t)b * NN + idx) * DD);
    ((float2*)(g_dec + b * DD))[n] = src[n];

    if (write_idx && n == 0)
        out[(size_t)BB * TT * NN + b * TT + t] = (float)idx;
}

// =====================================================================
extern "C" void kernel_launch(void* const* d_in, const int* in_sizes, int n_in,
                              void* d_out, int out_size)
{
    const float* te     = (const float*)d_in[0];   // [64,512,1024]
    const float* encdoc = (const float*)d_in[1];   // [64,1024]
    const float* W_ih   = (const float*)d_in[2];   // [2048,1024]
    const float* b_ih   = (const float*)d_in[3];   // [2048]
    const float* b_hh   = (const float*)d_in[4];   // [2048]
    const float* Wd     = (const float*)d_in[5];   // [512,512]
    const float* bd     = (const float*)d_in[6];   // [512]
    const float* We     = (const float*)d_in[7];   // [512,1024]
    const float* be     = (const float*)d_in[8];   // [512]
    const float* wr     = (const float*)d_in[9];   // [1,512] -> 512
    const float* br     = (const float*)d_in[10];  // [1]

    float* out = (float*)d_out;
    const int write_idx = (out_size >= BB * TT * NN + BB * TT) ? 1 : 0;

    // Phase 1: loop-invariant encoder projection, stored [b][e][n]
    enc_kernel<<<dim3(NN / 128, EE / 128, BB), 256>>>(te, We, be);

    // Step-0 decoder input
    init_dec_kernel<<<BB, 256>>>(encdoc);

    // Sequential pointer decode
    for (int t = 0; t < TT; t++) {
        hx_kernel<<<(BB * EE) / 8, 256>>>(W_ih, b_ih, b_hh);
        q_kernel<<<(BB * EE) / 8, 256>>>(Wd, bd);
        attn_kernel<<<dim3(NN / 64, BB), 256>>>(wr, br);
        softmax_kernel<<<BB, 512>>>(te, out, t, write_idx);
    }
}

// round 4
// speedup vs baseline: 1.2946x; 1.2946x over previous
#include <cuda_runtime.h>
#include <cuda_bf16.h>

// Problem constants
#define BB 64      // batch
#define NN 512     // tokens
#define EE 512     // embed dim
#define DD 1024    // 2E
#define TT 64      // decode steps

// ---------------- device scratch ----------------
__device__ float g_enc[(size_t)BB * EE * NN];   // [b][e][n]  64 MB, L2-resident
__device__ float g_dec_t[DD * BB];              // decoder input, TRANSPOSED [k][b]
__device__ float g_gpart[4][3][EE][BB];         // gate partials [kq][gate][e][b]
__device__ float g_hx_t[EE * BB];               // hx transposed [e(=k')][b]
__device__ float g_qpart[4][BB][EE];            // q partials [ks][b][e]
__device__ float g_scores[BB * NN];
__device__ float g_wsum;                        // sum of wr

// ---------------- packed fp32x2 helpers (sm_103a FFMA2) ----------------
__device__ __forceinline__ unsigned long long pack2(float x, float y) {
    unsigned long long r;
    asm("mov.b64 %0, {%1,%2};" : "=l"(r) : "f"(x), "f"(y));
    return r;
}
__device__ __forceinline__ void unpack2(unsigned long long v, float& x, float& y) {
    asm("mov.b64 {%0,%1}, %2;" : "=f"(x), "=f"(y) : "l"(v));
}
__device__ __forceinline__ void ffma2(unsigned long long& d, unsigned long long a, unsigned long long b) {
    asm("fma.rn.f32x2 %0, %1, %2, %0;" : "+l"(d) : "l"(a), "l"(b));
}
__device__ __forceinline__ float ex2a(float x) {
    float r; asm("ex2.approx.f32 %0, %1;" : "=f"(r) : "f"(x)); return r;
}
__device__ __forceinline__ float rcpa(float x) {
    float r; asm("rcp.approx.f32 %0, %1;" : "=f"(r) : "f"(x)); return r;
}

#define C2L 2.885390081777926f   // 2*log2(e)

// =====================================================================
// K1: enc[b][e][n] = be[e] + sum_d te[b][n][d] * We[e][d]
// (unchanged from R2 — measured near FFMA2 roofline)
// =====================================================================
__global__ __launch_bounds__(256) void enc_kernel(
    const float* __restrict__ te, const float* __restrict__ We,
    const float* __restrict__ be)
{
    const int b  = blockIdx.z;
    const int n0 = blockIdx.x * 128;
    const int e0 = blockIdx.y * 128;

    __shared__ __align__(16) float As[16][132];
    __shared__ __align__(16) float Bs[16][132];

    const int tid = threadIdx.x;
    const int ty  = tid >> 4;
    const int tx  = tid & 15;

    unsigned long long acc[8][4];
#pragma unroll
    for (int i = 0; i < 8; i++)
#pragma unroll
        for (int j = 0; j < 4; j++) acc[i][j] = 0ULL;

    const int lrow = tid >> 2;
    const int lk4  = (tid & 3) * 4;
    const float* Aptr = We + (size_t)(e0 + lrow) * DD + lk4;
    const float* Bptr = te + ((size_t)b * NN + (n0 + lrow)) * DD + lk4;

    for (int k0 = 0; k0 < DD; k0 += 16) {
        float4 a0 = *(const float4*)(Aptr + k0);
        float4 a1 = *(const float4*)(Aptr + k0 + (size_t)64 * DD);
        float4 c0 = *(const float4*)(Bptr + k0);
        float4 c1 = *(const float4*)(Bptr + k0 + (size_t)64 * DD);
        As[lk4 + 0][lrow]      = a0.x; As[lk4 + 1][lrow]      = a0.y;
        As[lk4 + 2][lrow]      = a0.z; As[lk4 + 3][lrow]      = a0.w;
        As[lk4 + 0][lrow + 64] = a1.x; As[lk4 + 1][lrow + 64] = a1.y;
        As[lk4 + 2][lrow + 64] = a1.z; As[lk4 + 3][lrow + 64] = a1.w;
        Bs[lk4 + 0][lrow]      = c0.x; Bs[lk4 + 1][lrow]      = c0.y;
        Bs[lk4 + 2][lrow]      = c0.z; Bs[lk4 + 3][lrow]      = c0.w;
        Bs[lk4 + 0][lrow + 64] = c1.x; Bs[lk4 + 1][lrow + 64] = c1.y;
        Bs[lk4 + 2][lrow + 64] = c1.z; Bs[lk4 + 3][lrow + 64] = c1.w;
        __syncthreads();

#pragma unroll
        for (int kk = 0; kk < 16; kk++) {
            float4 av0 = *(const float4*)&As[kk][ty * 8];
            float4 av1 = *(const float4*)&As[kk][ty * 8 + 4];
            float4 bv0 = *(const float4*)&Bs[kk][tx * 8];
            float4 bv1 = *(const float4*)&Bs[kk][tx * 8 + 4];
            unsigned long long bp0 = pack2(bv0.x, bv0.y);
            unsigned long long bp1 = pack2(bv0.z, bv0.w);
            unsigned long long bp2 = pack2(bv1.x, bv1.y);
            unsigned long long bp3 = pack2(bv1.z, bv1.w);
            float av[8] = {av0.x, av0.y, av0.z, av0.w, av1.x, av1.y, av1.z, av1.w};
#pragma unroll
            for (int i = 0; i < 8; i++) {
                unsigned long long ad = pack2(av[i], av[i]);
                ffma2(acc[i][0], ad, bp0);
                ffma2(acc[i][1], ad, bp1);
                ffma2(acc[i][2], ad, bp2);
                ffma2(acc[i][3], ad, bp3);
            }
        }
        __syncthreads();
    }

#pragma unroll
    for (int i = 0; i < 8; i++) {
        const int e = e0 + ty * 8 + i;
        const float bias = __ldg(&be[e]);
        float* orow = g_enc + ((size_t)b * EE + e) * NN + n0 + tx * 8;
#pragma unroll
        for (int j = 0; j < 4; j++) {
            float x, y;
            unpack2(acc[i][j], x, y);
            float2 v = make_float2(x + bias, y + bias);
            *(float2*)(orow + 2 * j) = v;
        }
    }
}

// =====================================================================
// K0: g_dec_t[k][b] <- encoded_document[b][k]; block 0 also reduces wr.
// grid 64, block 256
// =====================================================================
__global__ __launch_bounds__(256) void init_kernel(
    const float* __restrict__ encdoc, const float* __restrict__ wr)
{
    const int b = blockIdx.x, t = threadIdx.x;
#pragma unroll
    for (int i = 0; i < 4; i++) {
        const int k = i * 256 + t;
        g_dec_t[k * BB + b] = encdoc[(size_t)b * DD + k];
    }
    if (b == 0) {
        __shared__ float red[256];
        red[t] = __ldg(&wr[t]) + __ldg(&wr[t + 256]);
        __syncthreads();
#pragma unroll
        for (int o = 128; o > 0; o >>= 1) {
            if (t < o) red[t] += red[t + o];
            __syncthreads();
        }
        if (t == 0) g_wsum = red[0];
    }
}

// =====================================================================
// K2a: gate partials. grid 128 = 32 e-blocks x 4 k-quarters, block 256.
// Block covers 16 e x 64 b x 3 gates over a 256-wide k slice.
// Weight-stationary: W rows read once per block; x staged [kk][b] in smem.
// =====================================================================
__global__ __launch_bounds__(256) void gates_kernel(const float* __restrict__ W_ih)
{
    const int eb = blockIdx.x & 31, kq = blockIdx.x >> 5;
    const int e0 = eb * 16, kbase = kq * 256;

    __shared__ __align__(16) float xs[32][64];
    __shared__ __align__(16) float ws[16][32][4];

    const int t  = threadIdx.x;
    const int ec = t >> 4;       // 0..15 -> e
    const int bq = t & 15;       // 0..15 -> b group of 4

    unsigned long long acc[3][2];
#pragma unroll
    for (int g = 0; g < 3; g++) { acc[g][0] = 0ULL; acc[g][1] = 0ULL; }

    for (int c = 0; c < 8; c++) {
        const int kc = kbase + c * 32;
#pragma unroll
        for (int i = 0; i < 8; i++) {
            const int idx = i * 256 + t;
            const int b = idx & 63, kk = idx >> 6;
            xs[kk][b] = g_dec_t[(kc + kk) * BB + b];
        }
#pragma unroll
        for (int gi = 0; gi < 3; gi++) {
            const int row0 = (gi == 0 ? 0 : (gi == 1 ? 2 * EE : 3 * EE)) + e0;
#pragma unroll
            for (int j = 0; j < 2; j++) {
                const int idx = j * 256 + t;
                const int kk = idx & 31, ee = idx >> 5;
                ws[ee][kk][gi] = __ldg(&W_ih[(size_t)(row0 + ee) * DD + kc + kk]);
            }
        }
        __syncthreads();

#pragma unroll
        for (int kk = 0; kk < 32; kk++) {
            float4 xv = *(const float4*)&xs[kk][bq * 4];
            unsigned long long xp0 = pack2(xv.x, xv.y);
            unsigned long long xp1 = pack2(xv.z, xv.w);
            float4 wv = *(const float4*)&ws[ec][kk][0];
            unsigned long long w0 = pack2(wv.x, wv.x);
            unsigned long long w1 = pack2(wv.y, wv.y);
            unsigned long long w2 = pack2(wv.z, wv.z);
            ffma2(acc[0][0], w0, xp0); ffma2(acc[0][1], w0, xp1);
            ffma2(acc[1][0], w1, xp0); ffma2(acc[1][1], w1, xp1);
            ffma2(acc[2][0], w2, xp0); ffma2(acc[2][1], w2, xp1);
        }
        __syncthreads();
    }

#pragma unroll
    for (int g = 0; g < 3; g++) {
        float a, b2, c2, d2;
        unpack2(acc[g][0], a, b2);
        unpack2(acc[g][1], c2, d2);
        *(float4*)&g_gpart[kq][g][e0 + ec][bq * 4] = make_float4(a, b2, c2, d2);
    }
}

// =====================================================================
// K2b: reduce gate partials + biases + activation -> g_hx_t[e][b].
// grid 128, block 256 (32768 outputs). Accurate expf/tanhf (cheap here).
// =====================================================================
__global__ __launch_bounds__(256) void hx_act_kernel(
    const float* __restrict__ b_ih, const float* __restrict__ b_hh)
{
    const int idx = blockIdx.x * 256 + threadIdx.x;
    const int b = idx & 63, e = idx >> 6;
    float gi = __ldg(&b_ih[e])          + __ldg(&b_hh[e]);
    float gg = __ldg(&b_ih[2 * EE + e]) + __ldg(&b_hh[2 * EE + e]);
    float go = __ldg(&b_ih[3 * EE + e]) + __ldg(&b_hh[3 * EE + e]);
#pragma unroll
    for (int kq = 0; kq < 4; kq++) {
        gi += g_gpart[kq][0][e][b];
        gg += g_gpart[kq][1][e][b];
        go += g_gpart[kq][2][e][b];
    }
    const float c  = (1.f / (1.f + expf(-gi))) * tanhf(gg);
    const float hx = (1.f / (1.f + expf(-go))) * tanhf(c);
    g_hx_t[e * BB + b] = hx;
}

// =====================================================================
// K3: q partials. grid 128 = 32 e-blocks x 4 k-splits, block 256.
// Same weight-stationary structure over hx_t.
// =====================================================================
__global__ __launch_bounds__(256) void q_gemm_kernel(const float* __restrict__ Wd)
{
    const int eb = blockIdx.x & 31, ks = blockIdx.x >> 5;
    const int e0 = eb * 16, kbase = ks * 128;

    __shared__ __align__(16) float xs[32][64];
    __shared__ float ws[16][32];

    const int t = threadIdx.x, ec = t >> 4, bq = t & 15;
    unsigned long long acc0 = 0ULL, acc1 = 0ULL;

    for (int c = 0; c < 4; c++) {
        const int kc = kbase + c * 32;
#pragma unroll
        for (int i = 0; i < 8; i++) {
            const int idx = i * 256 + t;
            const int b = idx & 63, kk = idx >> 6;
            xs[kk][b] = g_hx_t[(kc + kk) * BB + b];
        }
#pragma unroll
        for (int j = 0; j < 2; j++) {
            const int idx = j * 256 + t;
            const int kk = idx & 31, ee = idx >> 5;
            ws[ee][kk] = __ldg(&Wd[(size_t)(e0 + ee) * EE + kc + kk]);
        }
        __syncthreads();

#pragma unroll
        for (int kk = 0; kk < 32; kk++) {
            float4 xv = *(const float4*)&xs[kk][bq * 4];
            const float w = ws[ec][kk];
            unsigned long long wp = pack2(w, w);
            ffma2(acc0, wp, pack2(xv.x, xv.y));
            ffma2(acc1, wp, pack2(xv.z, xv.w));
        }
        __syncthreads();
    }

    float a, b2, c2, d2;
    unpack2(acc0, a, b2);
    unpack2(acc1, c2, d2);
    const int b0 = bq * 4, e = e0 + ec;
    g_qpart[ks][b0 + 0][e] = a;
    g_qpart[ks][b0 + 1][e] = b2;
    g_qpart[ks][b0 + 2][e] = c2;
    g_qpart[ks][b0 + 3][e] = d2;
}

// =====================================================================
// K4: scores[b][n] = wsum - 2*sum_e wr_e * rcp(exp2(C2L*(enc+q)) + 1) + br
// (== sum_e wr_e * tanh(q_e + enc_en) + br, 2-MUFU tanh)
// Folds q-partial reduction + bd bias. grid (8, 64), block 256.
// =====================================================================
__global__ __launch_bounds__(256) void attn_kernel(
    const float* __restrict__ wr, const float* __restrict__ bd,
    const float* __restrict__ br)
{
    __shared__ float qc[EE];
    __shared__ float wsm[EE];
    __shared__ float part[4][64];

    const int b  = blockIdx.y;
    const int t  = threadIdx.x;
    const int nl = t & 63;
    const int qr = t >> 6;
    const int n  = blockIdx.x * 64 + nl;

#pragma unroll
    for (int j = 0; j < 2; j++) {
        const int e = j * 256 + t;
        const float q = __ldg(&bd[e]) + g_qpart[0][b][e] + g_qpart[1][b][e]
                        + g_qpart[2][b][e] + g_qpart[3][b][e];
        qc[e]  = C2L * q;
        wsm[e] = __ldg(&wr[e]);
    }
    __syncthreads();

    const float* p = g_enc + ((size_t)b * EE + qr * 128) * NN + n;
    float acc = 0.f;
#pragma unroll 8
    for (int e = 0; e < 128; e++) {
        const float v  = __ldg(p + (size_t)e * NN);
        const int   eg = (qr << 7) + e;
        const float a  = fmaf(C2L, v, qc[eg]);
        const float tt = ex2a(a);
        const float u  = rcpa(tt + 1.f);
        acc = fmaf(wsm[eg], u, acc);
    }
    part[qr][nl] = acc;
    __syncthreads();

    if (t < 64) {
        const float s = g_wsum
                      - 2.f * (part[0][t] + part[1][t] + part[2][t] + part[3][t])
                      + __ldg(br);
        g_scores[b * NN + blockIdx.x * 64 + t] = s;
    }
}

// =====================================================================
// K5: per-b log_softmax + argmax (first-index ties) + transposed gather.
// Warp-shuffle reductions. grid 64, block 512.
// =====================================================================
__global__ __launch_bounds__(512) void softmax_kernel(
    const float* __restrict__ te, float* __restrict__ out,
    int t_step, int write_idx)
{
    __shared__ float wm[16];
    __shared__ int   wi[16];
    __shared__ float wsum_[16];
    __shared__ float s_m;
    __shared__ int   s_i;
    __shared__ float s_lse;

    const int b = blockIdx.x, n = threadIdx.x;
    const int lane = n & 31, w = n >> 5;

    const float s = g_scores[b * NN + n];

    float m = s; int mi = n;
#pragma unroll
    for (int o = 16; o; o >>= 1) {
        const float om = __shfl_xor_sync(0xffffffffu, m, o);
        const int   oi = __shfl_xor_sync(0xffffffffu, mi, o);
        if (om > m || (om == m && oi < mi)) { m = om; mi = oi; }
    }
    if (lane == 0) { wm[w] = m; wi[w] = mi; }
    __syncthreads();
    if (w == 0) {
        float m2 = (lane < 16) ? wm[lane] : -3.4e38f;
        int   i2 = (lane < 16) ? wi[lane] : 0;
#pragma unroll
        for (int o = 8; o; o >>= 1) {
            const float om = __shfl_xor_sync(0xffffffffu, m2, o);
            const int   oi = __shfl_xor_sync(0xffffffffu, i2, o);
            if (om > m2 || (om == m2 && oi < i2)) { m2 = om; i2 = oi; }
        }
        if (lane == 0) { s_m = m2; s_i = i2; }
    }
    __syncthreads();
    const float mm  = s_m;
    const int   idx = s_i;

    float sum = expf(s - mm);
    const float ev = sum;
    (void)ev;
#pragma unroll
    for (int o = 16; o; o >>= 1) sum += __shfl_xor_sync(0xffffffffu, sum, o);
    if (lane == 0) wsum_[w] = sum;
    __syncthreads();
    if (w == 0) {
        float s2 = (lane < 16) ? wsum_[lane] : 0.f;
#pragma unroll
        for (int o = 8; o; o >>= 1) s2 += __shfl_xor_sync(0xffffffffu, s2, o);
        if (lane == 0) s_lse = mm + logf(s2);
    }
    __syncthreads();

    out[((size_t)b * TT + t_step) * NN + n] = s - s_lse;

    // gather next decoder input -> transposed g_dec_t[k][b]
    const float* src = te + ((size_t)b * NN + idx) * DD;
    g_dec_t[n * BB + b]          = src[n];
    g_dec_t[(n + 512) * BB + b]  = src[n + 512];

    if (write_idx && n == 0)
        out[(size_t)BB * TT * NN + b * TT + t_step] = (float)idx;
}

// =====================================================================
extern "C" void kernel_launch(void* const* d_in, const int* in_sizes, int n_in,
                              void* d_out, int out_size)
{
    const float* te     = (const float*)d_in[0];   // [64,512,1024]
    const float* encdoc = (const float*)d_in[1];   // [64,1024]
    const float* W_ih   = (const float*)d_in[2];   // [2048,1024]
    const float* b_ih   = (const float*)d_in[3];   // [2048]
    const float* b_hh   = (const float*)d_in[4];   // [2048]
    const float* Wd     = (const float*)d_in[5];   // [512,512]
    const float* bd     = (const float*)d_in[6];   // [512]
    const float* We     = (const float*)d_in[7];   // [512,1024]
    const float* be     = (const float*)d_in[8];   // [512]
    const float* wr     = (const float*)d_in[9];   // [1,512]
    const float* br     = (const float*)d_in[10];  // [1]

    float* out = (float*)d_out;
    const int write_idx = (out_size >= BB * TT * NN + BB * TT) ? 1 : 0;

    // Phase 1: loop-invariant encoder projection, stored [b][e][n]
    enc_kernel<<<dim3(NN / 128, EE / 128, BB), 256>>>(te, We, be);

    // Step-0 decoder input (transposed) + wr sum
    init_kernel<<<BB, 256>>>(encdoc, wr);

    // Sequential pointer decode
    for (int t = 0; t < TT; t++) {
        gates_kernel<<<128, 256>>>(W_ih);
        hx_act_kernel<<<128, 256>>>(b_ih, b_hh);
        q_gemm_kernel<<<128, 256>>>(Wd);
        attn_kernel<<<dim3(NN / 64, BB), 256>>>(wr, bd, br);
        softmax_kernel<<<BB, 512>>>(te, out, t, write_idx);
    }
}